// round 2
// baseline (speedup 1.0000x reference)
#include <cuda_runtime.h>

// Problem constants
#define BATCH   8
#define NPTS    4096
#define NP      1024     // npoint
#define NS      32       // nsample
#define INCH    64
#define MROWS   (BATCH*NP*NS)   // 262144 grouped rows
#define RAD2    0.04f
#define NSTATB  256      // blocks for stats reduction

// ---------------- device scratch (no cudaMalloc allowed) ----------------
__device__ float  g_Y0[MROWS*64];
__device__ float  g_Y1[MROWS*64];
__device__ float  g_Y2[MROWS*128];
__device__ float  g_nxyz[BATCH*NP*3];
__device__ int    g_gi[BATCH*NP*NS];
__device__ double g_part[NSTATB*128*2];
__device__ float  g_scale[128];
__device__ float  g_shift[128];

// ======================= 1) Farthest point sampling =======================
// One block per batch, 512 threads, 8 points/thread. xyz cached in smem (SoA),
// per-thread distance kept in registers. Argmax with first-index tie-break via
// key = (float_bits(dist) << 32) | (0xFFFFFFFF - idx).
__global__ void fps_kernel(const float* __restrict__ xyz,
                           float* __restrict__ out)
{
    extern __shared__ float sm[];
    float* xs = sm;
    float* ys = sm + NPTS;
    float* zs = sm + 2*NPTS;
    unsigned long long* wk = (unsigned long long*)(sm + 3*NPTS);
    int* farS = (int*)(wk + 16);

    const int b   = blockIdx.x;
    const int tid = threadIdx.x;
    const int lane = tid & 31, warp = tid >> 5;
    const float* X = xyz + (size_t)b * NPTS * 3;

    for (int i = tid; i < NPTS; i += 512) {
        xs[i] = X[i*3+0]; ys[i] = X[i*3+1]; zs[i] = X[i*3+2];
    }
    float dloc[8];
#pragma unroll
    for (int j = 0; j < 8; ++j) dloc[j] = 1e10f;
    __syncthreads();

    int far = 0;
    for (int it = 0; it < NP; ++it) {
        const float cx = xs[far], cy = ys[far], cz = zs[far];
        if (tid == 0) {
            const int o = (b*NP + it)*3;
            g_nxyz[o+0] = cx; g_nxyz[o+1] = cy; g_nxyz[o+2] = cz;
            out[o+0] = cx;    out[o+1] = cy;    out[o+2] = cz;
        }
        unsigned long long best = 0ull;
#pragma unroll
        for (int j = 0; j < 8; ++j) {
            const int p = tid + j*512;
            const float dx = xs[p]-cx, dy = ys[p]-cy, dz = zs[p]-cz;
            const float dd = dx*dx + dy*dy + dz*dz;
            const float nd = fminf(dloc[j], dd);
            dloc[j] = nd;
            const unsigned long long key =
                ((unsigned long long)__float_as_uint(nd) << 32) |
                (unsigned long long)(0xFFFFFFFFu - (unsigned)p);
            best = (key > best) ? key : best;
        }
#pragma unroll
        for (int off = 16; off >= 1; off >>= 1) {
            unsigned long long o = __shfl_xor_sync(0xFFFFFFFFu, best, off);
            best = (o > best) ? o : best;
        }
        if (lane == 0) wk[warp] = best;
        __syncthreads();
        if (warp == 0) {
            unsigned long long v = (lane < 16) ? wk[lane] : 0ull;
#pragma unroll
            for (int off = 8; off >= 1; off >>= 1) {
                unsigned long long o = __shfl_xor_sync(0xFFFFFFFFu, v, off);
                v = (o > v) ? o : v;
            }
            if (lane == 0) farS[0] = (int)(0xFFFFFFFFu - (unsigned)v);
        }
        __syncthreads();
        far = farS[0];
    }
}

// ======================= 2) Ball query =======================
// One warp per query point; scan points in ascending index order, keep first
// 32 inside radius; pad with first qualifying index. Matches jnp.sort+take.
__global__ void qb_kernel(const float* __restrict__ xyz)
{
    const int w    = (blockIdx.x * blockDim.x + threadIdx.x) >> 5; // 0..8191
    const int lane = threadIdx.x & 31;
    const int b = w >> 10;
    const float* X = xyz + (size_t)b * NPTS * 3;
    const float cx = g_nxyz[w*3+0], cy = g_nxyz[w*3+1], cz = g_nxyz[w*3+2];
    int* g = g_gi + w*NS;

    int cnt = 0, first = -1;
    for (int r = 0; r < NPTS/32; ++r) {
        const int n = r*32 + lane;
        const float dx = X[n*3+0]-cx, dy = X[n*3+1]-cy, dz = X[n*3+2]-cz;
        const float d2 = dx*dx + dy*dy + dz*dz;
        const bool in = (d2 <= RAD2);
        const unsigned m = __ballot_sync(0xFFFFFFFFu, in);
        if (first < 0 && m) first = r*32 + __ffs(m) - 1;
        const int pos = cnt + __popc(m & ((1u << lane) - 1u));
        if (in && pos < NS) g[pos] = n;
        cnt += __popc(m);
        if (cnt >= NS) break;
    }
    for (int i = cnt + lane; i < NS; i += 32) g[i] = first;
}

// ======================= 3) Linear (+fused BN/ReLU on input) =======================
// Block = 128 rows x N cols, 256 threads, thread tile 8 rows x (N/16) cols.
// LAYER 0: gathers concat(grouped_xyz - center, grouped_points) on the fly.
// LAYER 1/2: applies BN+ReLU of previous layer while loading the tile.
// Bias is omitted: it cancels exactly inside the batch-norm.
template<int LAYER>
__global__ __launch_bounds__(256) void mm_kernel(const float* __restrict__ xyz,
                                                 const float* __restrict__ pts,
                                                 const float* __restrict__ W)
{
    constexpr int K   = (LAYER == 0) ? 67 : 64;
    constexpr int N   = (LAYER == 2) ? 128 : 64;
    constexpr int CPT = N / 16;
    constexpr int KP  = K + 1;

    const float* __restrict__ Yp = (LAYER == 1) ? g_Y0 : g_Y1;
    float* __restrict__ Y = (LAYER == 0) ? g_Y0 : ((LAYER == 1) ? g_Y1 : g_Y2);

    extern __shared__ float smf[];
    float* Wt = smf;             // [K][N]  (transposed weights)
    float* Xs = smf + K * N;     // [128][K+1]

    __shared__ int   sIdx[128];
    __shared__ int   sB[128];
    __shared__ float sCtr[128*3];

    const int tid = threadIdx.x;
    const int blk = blockIdx.x;

    // transpose weights into smem: Wt[k*N+n] = W[n*K+k]
    for (int i = tid; i < K*N; i += 256) {
        const int k = i / N, n = i - k*N;
        Wt[i] = W[n*K + k];
    }

    if (LAYER == 0) {
        if (tid < 128) {
            const int r = blk*128 + tid;
            const int b = r >> 15;
            const int s = (r >> 5) & 1023;
            const int kk = r & 31;
            sIdx[tid] = g_gi[((b << 10) + s)*NS + kk];
            sB[tid]   = b;
            const int o = ((b << 10) + s)*3;
            sCtr[tid*3+0] = g_nxyz[o+0];
            sCtr[tid*3+1] = g_nxyz[o+1];
            sCtr[tid*3+2] = g_nxyz[o+2];
        }
        __syncthreads();
        for (int i = tid; i < 128*K; i += 256) {
            const int lr = i / K, c = i - lr*K;
            const int idx = sIdx[lr];
            const int b = sB[lr];
            float v;
            if (c < 3) v = xyz[((size_t)b*NPTS + idx)*3 + c] - sCtr[lr*3 + c];
            else       v = pts[((size_t)b*NPTS + idx)*INCH + (c - 3)];
            Xs[lr*KP + c] = v;
        }
    } else {
        for (int i = tid; i < 128*K; i += 256) {
            const int lr = i / K, c = i - lr*K;
            const size_t r = (size_t)blk*128 + lr;
            float v = Yp[r*K + c];
            v = fmaxf(v * g_scale[c] + g_shift[c], 0.f);
            Xs[lr*KP + c] = v;
        }
    }
    __syncthreads();

    const int tx = tid & 15;       // 16 col groups
    const int ty = tid >> 4;       // 16 row groups of 8
    float acc[8][CPT];
#pragma unroll
    for (int i = 0; i < 8; ++i)
#pragma unroll
        for (int j = 0; j < CPT; ++j) acc[i][j] = 0.f;

#pragma unroll 4
    for (int k = 0; k < K; ++k) {
        float a[8];
#pragma unroll
        for (int i = 0; i < 8; ++i) a[i] = Xs[(ty*8 + i)*KP + k];
        float bv[CPT];
        {
            const float4 b0 = *(const float4*)(&Wt[k*N + tx*CPT]);
            bv[0] = b0.x; bv[1] = b0.y; bv[2] = b0.z; bv[3] = b0.w;
            if (CPT == 8) {
                const float4 b1 = *(const float4*)(&Wt[k*N + tx*CPT + 4]);
                bv[4] = b1.x; bv[5] = b1.y; bv[6] = b1.z; bv[7] = b1.w;
            }
        }
#pragma unroll
        for (int i = 0; i < 8; ++i)
#pragma unroll
            for (int j = 0; j < CPT; ++j)
                acc[i][j] = fmaf(a[i], bv[j], acc[i][j]);
    }

#pragma unroll
    for (int i = 0; i < 8; ++i) {
        const size_t row = (size_t)blk*128 + ty*8 + i;
        float* yp = Y + row*N + tx*CPT;
        *(float4*)yp = make_float4(acc[i][0], acc[i][1], acc[i][2], acc[i][3]);
        if (CPT == 8)
            *(float4*)(yp + 4) = make_float4(acc[i][4], acc[i][5], acc[i][6], acc[i][7]);
    }
}

// ======================= 4) BN statistics (deterministic, no atomics) =======================
template<int LAYER>
__global__ void stats_kernel()
{
    constexpr int C = (LAYER == 2) ? 128 : 64;
    constexpr int R = 256 / C;
    const float* __restrict__ Y = (LAYER == 0) ? g_Y0 : ((LAYER == 1) ? g_Y1 : g_Y2);

    __shared__ double sd[256], sq[256];
    const int tid = threadIdx.x, blk = blockIdx.x;
    const int c = tid % C, rg = tid / C;
    const int rowsPerBlk = MROWS / NSTATB;   // 1024

    double s = 0.0, q = 0.0;
    for (int r = rg; r < rowsPerBlk; r += R) {
        const double v = (double)Y[(size_t)(blk*rowsPerBlk + r)*C + c];
        s += v; q += v*v;
    }
    sd[tid] = s; sq[tid] = q;
    __syncthreads();
    if (tid < C) {
        double ts = sd[tid], tq = sq[tid];
#pragma unroll
        for (int g = 1; g < R; ++g) { ts += sd[tid + g*C]; tq += sq[tid + g*C]; }
        g_part[(blk*C + c)*2 + 0] = ts;
        g_part[(blk*C + c)*2 + 1] = tq;
    }
}

template<int C>
__global__ void finalize_kernel(const float* __restrict__ gam,
                                const float* __restrict__ bet)
{
    const int c = threadIdx.x;
    if (c >= C) return;
    double s = 0.0, q = 0.0;
    for (int blk = 0; blk < NSTATB; ++blk) {
        s += g_part[(blk*C + c)*2 + 0];
        q += g_part[(blk*C + c)*2 + 1];
    }
    const double mu  = s / (double)MROWS;
    const double var = q / (double)MROWS - mu*mu;
    const float rs = (float)rsqrt(var + 1e-5);
    const float sc = gam[c] * rs;
    g_scale[c] = sc;
    g_shift[c] = bet[c] - (float)mu * sc;
}

// ======================= 5) BN+ReLU + max-pool over samples =======================
__global__ void pool_kernel(float* __restrict__ out)
{
    const int bs = blockIdx.x;       // 0..8191 (b*1024+s)
    const int c  = threadIdx.x;      // 0..127
    const float sc = g_scale[c], sh = g_shift[c];
    const float* y = g_Y2 + (size_t)bs*NS*128 + c;
    float m = 0.f;                   // relu outputs are >= 0
#pragma unroll 8
    for (int k = 0; k < NS; ++k)
        m = fmaxf(m, fmaxf(y[(size_t)k*128]*sc + sh, 0.f));
    out[BATCH*NP*3 + (size_t)bs*128 + c] = m;
}

// ======================= launch =======================
extern "C" void kernel_launch(void* const* d_in, const int* in_sizes, int n_in,
                              void* d_out, int out_size)
{
    const float* xyz = (const float*)d_in[0];
    const float* pts = (const float*)d_in[1];
    const float* w0  = (const float*)d_in[2];
    const float* gm0 = (const float*)d_in[4];
    const float* bt0 = (const float*)d_in[5];
    const float* w1  = (const float*)d_in[6];
    const float* gm1 = (const float*)d_in[8];
    const float* bt1 = (const float*)d_in[9];
    const float* w2  = (const float*)d_in[10];
    const float* gm2 = (const float*)d_in[12];
    const float* bt2 = (const float*)d_in[13];
    float* out = (float*)d_out;

    // opt-in shared memory sizes
    cudaFuncSetAttribute(fps_kernel, cudaFuncAttributeMaxDynamicSharedMemorySize, 49536);
    cudaFuncSetAttribute(mm_kernel<0>, cudaFuncAttributeMaxDynamicSharedMemorySize, 51968);
    cudaFuncSetAttribute(mm_kernel<1>, cudaFuncAttributeMaxDynamicSharedMemorySize, 49664);
    cudaFuncSetAttribute(mm_kernel<2>, cudaFuncAttributeMaxDynamicSharedMemorySize, 66048);

    fps_kernel<<<BATCH, 512, 49536>>>(xyz, out);
    qb_kernel<<<(BATCH*NP*32)/256, 256>>>(xyz);

    mm_kernel<0><<<MROWS/128, 256, 51968>>>(xyz, pts, w0);
    stats_kernel<0><<<NSTATB, 256>>>();
    finalize_kernel<64><<<1, 64>>>(gm0, bt0);

    mm_kernel<1><<<MROWS/128, 256, 49664>>>(xyz, pts, w1);
    stats_kernel<1><<<NSTATB, 256>>>();
    finalize_kernel<64><<<1, 64>>>(gm1, bt1);

    mm_kernel<2><<<MROWS/128, 256, 66048>>>(xyz, pts, w2);
    stats_kernel<2><<<NSTATB, 256>>>();
    finalize_kernel<128><<<1, 128>>>(gm2, bt2);

    pool_kernel<<<BATCH*NP, 128>>>(out);
}

// round 3
// speedup vs baseline: 1.5389x; 1.5389x over previous
#include <cuda_runtime.h>

// Problem constants
#define BATCH   8
#define NPTS    4096
#define NP      1024
#define NS      32
#define INCH    64
#define MROWS   (BATCH*NP*NS)   // 262144 grouped rows
#define NQ      (BATCH*NP)      // 8192 queries
#define NSRC    (BATCH*NPTS)    // 32768 source points
#define RAD2    0.04f

typedef unsigned long long ull;

// ---------------- device scratch ----------------
__device__ float  g_F[NSRC*64];        // per-source-point layer0 partial (8MB, L2 resident)
__device__ float  g_Y1[(size_t)MROWS*64]; // layer1 output (64MB)
__device__ float  g_max[NQ*128];       // per-query max of layer2 pre-BN
__device__ float  g_nxyz[NQ*3];
__device__ int    g_gi[MROWS];
__device__ float2 g_p0[256*64];
__device__ float2 g_p1[2048*64];
__device__ float2 g_p2[2048*128];
__device__ float  g_sc0[64], g_sh0[64];
__device__ float  g_sc1[64], g_sh1[64];
__device__ float  g_sc2[128], g_sh2[128];

// ---------------- f32x2 helpers ----------------
__device__ __forceinline__ void fma2(ull& d, ull a, ull b) {
    asm("fma.rn.f32x2 %0, %1, %2, %0;" : "+l"(d) : "l"(a), "l"(b));
}
__device__ __forceinline__ float2 u2f2(ull v) {
    float2 r; asm("mov.b64 {%0, %1}, %2;" : "=f"(r.x), "=f"(r.y) : "l"(v)); return r;
}

// ======================= 1) Farthest point sampling =======================
__global__ void fps_kernel(const float* __restrict__ xyz, float* __restrict__ out)
{
    extern __shared__ float sm[];
    float* xs = sm;
    float* ys = sm + NPTS;
    float* zs = sm + 2*NPTS;
    ull* wk = (ull*)(sm + 3*NPTS);
    int* farS = (int*)(wk + 16);

    const int b   = blockIdx.x;
    const int tid = threadIdx.x;
    const int lane = tid & 31, warp = tid >> 5;
    const float* X = xyz + (size_t)b * NPTS * 3;

    for (int i = tid; i < NPTS; i += 512) {
        xs[i] = X[i*3+0]; ys[i] = X[i*3+1]; zs[i] = X[i*3+2];
    }
    float dloc[8];
#pragma unroll
    for (int j = 0; j < 8; ++j) dloc[j] = 1e10f;
    __syncthreads();

    int far = 0;
    for (int it = 0; it < NP; ++it) {
        const float cx = xs[far], cy = ys[far], cz = zs[far];
        if (tid == 0) {
            const int o = (b*NP + it)*3;
            g_nxyz[o+0] = cx; g_nxyz[o+1] = cy; g_nxyz[o+2] = cz;
            out[o+0] = cx;    out[o+1] = cy;    out[o+2] = cz;
        }
        ull best = 0ull;
#pragma unroll
        for (int j = 0; j < 8; ++j) {
            const int p = tid + j*512;
            const float dx = xs[p]-cx, dy = ys[p]-cy, dz = zs[p]-cz;
            const float dd = dx*dx + dy*dy + dz*dz;
            const float nd = fminf(dloc[j], dd);
            dloc[j] = nd;
            const ull key = ((ull)__float_as_uint(nd) << 32) |
                            (ull)(0xFFFFFFFFu - (unsigned)p);
            best = (key > best) ? key : best;
        }
#pragma unroll
        for (int off = 16; off >= 1; off >>= 1) {
            ull o = __shfl_xor_sync(0xFFFFFFFFu, best, off);
            best = (o > best) ? o : best;
        }
        if (lane == 0) wk[warp] = best;
        __syncthreads();
        if (warp == 0) {
            ull v = (lane < 16) ? wk[lane] : 0ull;
#pragma unroll
            for (int off = 8; off >= 1; off >>= 1) {
                ull o = __shfl_xor_sync(0xFFFFFFFFu, v, off);
                v = (o > v) ? o : v;
            }
            if (lane == 0) farS[0] = (int)(0xFFFFFFFFu - (unsigned)v);
        }
        __syncthreads();
        far = farS[0];
    }
}

// ======================= 2) Ball query =======================
__global__ void qb_kernel(const float* __restrict__ xyz)
{
    const int w    = (blockIdx.x * blockDim.x + threadIdx.x) >> 5;
    const int lane = threadIdx.x & 31;
    const int b = w >> 10;
    const float* X = xyz + (size_t)b * NPTS * 3;
    const float cx = g_nxyz[w*3+0], cy = g_nxyz[w*3+1], cz = g_nxyz[w*3+2];
    int* g = g_gi + w*NS;

    int cnt = 0, first = -1;
    for (int r = 0; r < NPTS/32; ++r) {
        const int n = r*32 + lane;
        const float dx = X[n*3+0]-cx, dy = X[n*3+1]-cy, dz = X[n*3+2]-cz;
        const float d2 = dx*dx + dy*dy + dz*dz;
        const bool in = (d2 <= RAD2);
        const unsigned m = __ballot_sync(0xFFFFFFFFu, in);
        if (first < 0 && m) first = r*32 + __ffs(m) - 1;
        const int pos = cnt + __popc(m & ((1u << lane) - 1u));
        if (in && pos < NS) g[pos] = n;
        cnt += __popc(m);
        if (cnt >= NS) break;
    }
    for (int i = cnt + lane; i < NS; i += 32) g[i] = first;
}

// ======================= 3) F precompute: F = concat(xyz, pts) @ W0^T =======================
// 32768 rows x 64 out, K=67. f32x2 GEMM, transposed-X smem, duplicated weights.
__global__ __launch_bounds__(256) void fprep_kernel(const float* __restrict__ xyz,
                                                    const float* __restrict__ pts,
                                                    const float* __restrict__ W)
{
    extern __shared__ float smf[];
    float* XsT = smf;               // [67][130]
    float* WtD = smf + 67*130;      // [67][128]  duplicated pairs
    const int tid = threadIdx.x, blk = blockIdx.x;

    for (int i = tid; i < 67*64; i += 256) {
        const int n = i / 67, k = i - n*67;
        const float w = W[i];
        WtD[k*128 + 2*n] = w; WtD[k*128 + 2*n + 1] = w;
    }
    for (int i = tid; i < 128*67; i += 256) {
        const int lr = i / 67, c = i - lr*67;
        const int row = blk*128 + lr;
        const float v = (c < 3) ? xyz[row*3 + c] : pts[(size_t)row*64 + (c-3)];
        XsT[c*130 + lr] = v;
    }
    __syncthreads();

    const int tx = tid & 15, ty = tid >> 4;
    ull acc[4][4];
#pragma unroll
    for (int i = 0; i < 4; ++i)
#pragma unroll
        for (int j = 0; j < 4; ++j) acc[i][j] = 0ull;

#pragma unroll 4
    for (int k = 0; k < 67; ++k) {
        ull a[4], bv[4];
#pragma unroll
        for (int i2 = 0; i2 < 4; ++i2)
            a[i2] = *(const ull*)&XsT[k*130 + ty*8 + 2*i2];
#pragma unroll
        for (int j = 0; j < 4; ++j)
            bv[j] = *(const ull*)&WtD[k*128 + 2*(tx + 16*j)];
#pragma unroll
        for (int i2 = 0; i2 < 4; ++i2)
#pragma unroll
            for (int j = 0; j < 4; ++j) fma2(acc[i2][j], a[i2], bv[j]);
    }

    const int base = blk*128 + ty*8;
#pragma unroll
    for (int i2 = 0; i2 < 4; ++i2) {
        const int r0 = base + 2*i2;
#pragma unroll
        for (int j = 0; j < 4; ++j) {
            const float2 v = u2f2(acc[i2][j]);
            const int col = tx + 16*j;
            g_F[(size_t)r0*64 + col]     = v.x;
            g_F[(size_t)(r0+1)*64 + col] = v.y;
        }
    }
}

// ======================= 4) stats of layer0 (gathered F - C) =======================
__global__ __launch_bounds__(256) void stats0_kernel(const float* __restrict__ w0)
{
    __shared__ float sw[64*3];
    __shared__ float sd[4*64], sq_[4*64];
    const int tid = threadIdx.x, blk = blockIdx.x;
    for (int i = tid; i < 192; i += 256) sw[i] = w0[(i/3)*67 + (i%3)];
    __syncthreads();

    const int c = tid & 63, rg = tid >> 6;
    float s0 = 0.f, s1 = 0.f, q0 = 0.f, q1 = 0.f;
    int t = 0;
    for (int r = rg; r < 1024; r += 4, t ^= 1) {
        const int row = blk*1024 + r;
        const int b = row >> 15;
        const int qg = row >> 5;
        const int idx = g_gi[row];
        const float Cc = g_nxyz[qg*3+0]*sw[c*3+0]
                       + g_nxyz[qg*3+1]*sw[c*3+1]
                       + g_nxyz[qg*3+2]*sw[c*3+2];
        const float v = g_F[(((size_t)b<<12) + idx)*64 + c] - Cc;
        if (t) { s1 += v; q1 = fmaf(v, v, q1); }
        else   { s0 += v; q0 = fmaf(v, v, q0); }
    }
    sd[rg*64+c] = s0 + s1; sq_[rg*64+c] = q0 + q1;
    __syncthreads();
    if (tid < 64) {
        float s = sd[tid] + sd[64+tid] + sd[128+tid] + sd[192+tid];
        float q = sq_[tid] + sq_[64+tid] + sq_[128+tid] + sq_[192+tid];
        g_p0[blk*64 + tid] = make_float2(s, q);
    }
}

// ======================= finalize BN params (per-channel block) =======================
__global__ void finalize_kernel(int layer, int nblk,
                                const float* __restrict__ gam,
                                const float* __restrict__ bet)
{
    const float2* part = (layer == 0) ? g_p0 : ((layer == 1) ? g_p1 : g_p2);
    const int C = (layer == 2) ? 128 : 64;
    const int c = blockIdx.x;
    const int tid = threadIdx.x;
    __shared__ double sd[256], sq_[256];
    double s = 0.0, q = 0.0;
    for (int i = tid; i < nblk; i += 256) {
        const float2 v = part[i*C + c];
        s += (double)v.x; q += (double)v.y;
    }
    sd[tid] = s; sq_[tid] = q;
    __syncthreads();
    for (int off = 128; off; off >>= 1) {
        if (tid < off) { sd[tid] += sd[tid+off]; sq_[tid] += sq_[tid+off]; }
        __syncthreads();
    }
    if (tid == 0) {
        const double mu  = sd[0] / (double)MROWS;
        const double var = sq_[0] / (double)MROWS - mu*mu;
        const float rs = (float)rsqrt(var + 1e-5);
        const float sc = gam[c] * rs;
        if (layer == 0)      { g_sc0[c] = sc; g_sh0[c] = bet[c] - (float)mu*sc; }
        else if (layer == 1) { g_sc1[c] = sc; g_sh1[c] = bet[c] - (float)mu*sc; }
        else                 { g_sc2[c] = sc; g_sh2[c] = bet[c] - (float)mu*sc; }
    }
}

// ======================= 5) mm1: gather(F)-C -> bn0/relu -> @W1^T, + stats epilogue =======================
__global__ __launch_bounds__(256) void mm1_kernel(const float* __restrict__ w0,
                                                  const float* __restrict__ W)
{
    extern __shared__ float smf[];
    float* XsT = smf;               // [64][130]
    float* WtD = smf + 64*130;      // [64][128]
    float* ssum = WtD;              // alias after GEMM: [16][64]
    float* ssq  = WtD + 16*64;      // [16][64]
    __shared__ float sW0x[64*3];
    __shared__ float sCtr[4*3];
    __shared__ int   sIdx[128];

    const int tid = threadIdx.x, blk = blockIdx.x;

    for (int i = tid; i < 64*64; i += 256) {
        const int n = i >> 6, k = i & 63;
        const float w = W[i];
        WtD[k*128 + 2*n] = w; WtD[k*128 + 2*n + 1] = w;
    }
    if (tid < 192) sW0x[tid] = w0[(tid/3)*67 + (tid%3)];
    if (tid < 12)  sCtr[tid] = g_nxyz[(blk*4 + tid/3)*3 + (tid%3)];
    if (tid < 128) sIdx[tid] = g_gi[blk*128 + tid];
    __syncthreads();

    for (int i = tid; i < 128*64; i += 256) {
        const int c = i & 63, lr = i >> 6;
        const int row = blk*128 + lr;
        const int b = row >> 15;
        const int g = lr >> 5;
        const int idx = sIdx[lr];
        const float Cc = sCtr[g*3+0]*sW0x[c*3+0]
                       + sCtr[g*3+1]*sW0x[c*3+1]
                       + sCtr[g*3+2]*sW0x[c*3+2];
        float v = g_F[(((size_t)b<<12) + idx)*64 + c] - Cc;
        v = fmaxf(fmaf(v, g_sc0[c], g_sh0[c]), 0.f);
        XsT[c*130 + lr] = v;
    }
    __syncthreads();

    const int tx = tid & 15, ty = tid >> 4;
    ull acc[4][4];
#pragma unroll
    for (int i = 0; i < 4; ++i)
#pragma unroll
        for (int j = 0; j < 4; ++j) acc[i][j] = 0ull;

#pragma unroll 4
    for (int k = 0; k < 64; ++k) {
        ull a[4], bv[4];
#pragma unroll
        for (int i2 = 0; i2 < 4; ++i2)
            a[i2] = *(const ull*)&XsT[k*130 + ty*8 + 2*i2];
#pragma unroll
        for (int j = 0; j < 4; ++j)
            bv[j] = *(const ull*)&WtD[k*128 + 2*(tx + 16*j)];
#pragma unroll
        for (int i2 = 0; i2 < 4; ++i2)
#pragma unroll
            for (int j = 0; j < 4; ++j) fma2(acc[i2][j], a[i2], bv[j]);
    }

    // store Y1 + local stats (fixed order => deterministic)
    float ls[4], lq[4];
    const int base = blk*128 + ty*8;
#pragma unroll
    for (int j = 0; j < 4; ++j) {
        const int col = tx + 16*j;
        float s = 0.f, q = 0.f;
#pragma unroll
        for (int i2 = 0; i2 < 4; ++i2) {
            const float2 v = u2f2(acc[i2][j]);
            const int r0 = base + 2*i2;
            g_Y1[(size_t)r0*64 + col]     = v.x;
            g_Y1[(size_t)(r0+1)*64 + col] = v.y;
            s += v.x; s += v.y;
            q = fmaf(v.x, v.x, q); q = fmaf(v.y, v.y, q);
        }
        ls[j] = s; lq[j] = q;
    }
    __syncthreads();   // WtD no longer needed; safe to alias
#pragma unroll
    for (int j = 0; j < 4; ++j) {
        const int col = tx + 16*j;
        ssum[ty*64 + col] = ls[j];
        ssq [ty*64 + col] = lq[j];
    }
    __syncthreads();
    if (tid < 64) {
        float s = 0.f, q = 0.f;
#pragma unroll
        for (int t = 0; t < 16; ++t) { s += ssum[t*64 + tid]; q += ssq[t*64 + tid]; }
        g_p1[blk*64 + tid] = make_float2(s, q);
    }
}

// ======================= 6) mm2: bn1/relu(Y1) @ W2^T, + stats + in-block max-pool =======================
__global__ __launch_bounds__(256) void mm2_kernel(const float* __restrict__ W)
{
    extern __shared__ float smf[];
    float* XsT = smf;               // [64][130]
    float* WtD = smf + 64*130;      // [64][256]
    float* ssum = WtD;              // alias: [16][128]
    float* ssq  = WtD + 16*128;
    float* smax = WtD + 32*128;

    const int tid = threadIdx.x, blk = blockIdx.x;

    for (int i = tid; i < 128*64; i += 256) {
        const int n = i >> 6, k = i & 63;
        const float w = W[i];
        WtD[k*256 + 2*n] = w; WtD[k*256 + 2*n + 1] = w;
    }
    for (int i = tid; i < 128*64; i += 256) {
        const int c = i & 63, lr = i >> 6;
        const size_t row = (size_t)blk*128 + lr;
        float v = g_Y1[row*64 + c];
        v = fmaxf(fmaf(v, g_sc1[c], g_sh1[c]), 0.f);
        XsT[c*130 + lr] = v;
    }
    __syncthreads();

    const int tx = tid & 15, ty = tid >> 4;
    ull acc[4][8];
#pragma unroll
    for (int i = 0; i < 4; ++i)
#pragma unroll
        for (int j = 0; j < 8; ++j) acc[i][j] = 0ull;

#pragma unroll 2
    for (int k = 0; k < 64; ++k) {
        ull a[4], bv[8];
#pragma unroll
        for (int i2 = 0; i2 < 4; ++i2)
            a[i2] = *(const ull*)&XsT[k*130 + ty*8 + 2*i2];
#pragma unroll
        for (int j = 0; j < 8; ++j)
            bv[j] = *(const ull*)&WtD[k*256 + 2*(tx + 16*j)];
#pragma unroll
        for (int i2 = 0; i2 < 4; ++i2)
#pragma unroll
            for (int j = 0; j < 8; ++j) fma2(acc[i2][j], a[i2], bv[j]);
    }

    // local stats + max over this thread's 8 rows (all rows in one query group)
    float ls[8], lq[8], lm[8];
#pragma unroll
    for (int j = 0; j < 8; ++j) {
        float s = 0.f, q = 0.f, m = -3.4e38f;
#pragma unroll
        for (int i2 = 0; i2 < 4; ++i2) {
            const float2 v = u2f2(acc[i2][j]);
            s += v.x; s += v.y;
            q = fmaf(v.x, v.x, q); q = fmaf(v.y, v.y, q);
            m = fmaxf(m, fmaxf(v.x, v.y));
        }
        ls[j] = s; lq[j] = q; lm[j] = m;
    }
    __syncthreads();
#pragma unroll
    for (int j = 0; j < 8; ++j) {
        const int col = tx + 16*j;
        ssum[ty*128 + col] = ls[j];
        ssq [ty*128 + col] = lq[j];
        smax[ty*128 + col] = lm[j];
    }
    __syncthreads();
    if (tid < 128) {
        float s = 0.f, q = 0.f;
#pragma unroll
        for (int t = 0; t < 16; ++t) { s += ssum[t*128 + tid]; q += ssq[t*128 + tid]; }
        g_p2[blk*128 + tid] = make_float2(s, q);
    }
    for (int w = tid; w < 512; w += 256) {
        const int g = w >> 7, col = w & 127;
        float m = smax[(4*g+0)*128 + col];
        m = fmaxf(m, smax[(4*g+1)*128 + col]);
        m = fmaxf(m, smax[(4*g+2)*128 + col]);
        m = fmaxf(m, smax[(4*g+3)*128 + col]);
        g_max[(blk*4 + g)*128 + col] = m;
    }
}

// ======================= 7) final pool: bn2+relu on per-query max =======================
__global__ void pool_kernel(float* __restrict__ out)
{
    const int i = blockIdx.x * 1024 + threadIdx.x;   // < 8192*128
    const int c = i & 127;
    const float v = fmaxf(fmaf(g_max[i], g_sc2[c], g_sh2[c]), 0.f);
    out[NQ*3 + i] = v;
}

// ======================= launch =======================
extern "C" void kernel_launch(void* const* d_in, const int* in_sizes, int n_in,
                              void* d_out, int out_size)
{
    const float* xyz = (const float*)d_in[0];
    const float* pts = (const float*)d_in[1];
    const float* w0  = (const float*)d_in[2];
    const float* gm0 = (const float*)d_in[4];
    const float* bt0 = (const float*)d_in[5];
    const float* w1  = (const float*)d_in[6];
    const float* gm1 = (const float*)d_in[8];
    const float* bt1 = (const float*)d_in[9];
    const float* w2  = (const float*)d_in[10];
    const float* gm2 = (const float*)d_in[12];
    const float* bt2 = (const float*)d_in[13];
    float* out = (float*)d_out;

    const int smF  = 67*130*4 + 67*128*4;   // 69144
    const int smM1 = 64*130*4 + 64*128*4;   // 66048
    const int smM2 = 64*130*4 + 64*256*4;   // 98816

    cudaFuncSetAttribute(fps_kernel,  cudaFuncAttributeMaxDynamicSharedMemorySize, 49536);
    cudaFuncSetAttribute(fprep_kernel, cudaFuncAttributeMaxDynamicSharedMemorySize, smF);
    cudaFuncSetAttribute(mm1_kernel,  cudaFuncAttributeMaxDynamicSharedMemorySize, smM1);
    cudaFuncSetAttribute(mm2_kernel,  cudaFuncAttributeMaxDynamicSharedMemorySize, smM2);

    fprep_kernel<<<NSRC/128, 256, smF>>>(xyz, pts, w0);
    fps_kernel<<<BATCH, 512, 49536>>>(xyz, out);
    qb_kernel<<<(NQ*32)/256, 256>>>(xyz);

    stats0_kernel<<<256, 256>>>(w0);
    finalize_kernel<<<64, 256>>>(0, 256, gm0, bt0);

    mm1_kernel<<<MROWS/128, 256, smM1>>>(w0, w1);
    finalize_kernel<<<64, 256>>>(1, 2048, gm1, bt1);

    mm2_kernel<<<MROWS/128, 256, smM2>>>(w2);
    finalize_kernel<<<128, 256>>>(2, 2048, gm2, bt2);

    pool_kernel<<<(NQ*128)/1024, 1024>>>(out);
}

// round 4
// speedup vs baseline: 1.5448x; 1.0039x over previous
#include <cuda_runtime.h>

// Problem constants
#define BATCH   8
#define NPTS    4096
#define NP      1024
#define NS      32
#define INCH    64
#define MROWS   (BATCH*NP*NS)   // 262144 grouped rows
#define NQ      (BATCH*NP)      // 8192 queries
#define NSRC    (BATCH*NPTS)    // 32768 source points
#define RAD2    0.04f

typedef unsigned long long ull;

// ---------------- device scratch ----------------
__device__ float  g_F[NSRC*64];        // per-source-point layer0 partial (8MB, L2 resident)
__device__ float  g_Y1[(size_t)MROWS*64]; // layer1 output (64MB)
__device__ float  g_max[NQ*128];       // per-query max of layer2 pre-BN
__device__ float  g_nxyz[NQ*3];
__device__ int    g_gi[MROWS];
__device__ float2 g_p0[256*64];
__device__ float2 g_p1[2048*64];
__device__ float2 g_p2[2048*128];
__device__ float  g_sc0[64], g_sh0[64];
__device__ float  g_sc1[64], g_sh1[64];
__device__ float  g_sc2[128], g_sh2[128];

// ---------------- f32x2 helpers ----------------
__device__ __forceinline__ void fma2(ull& d, ull a, ull b) {
    asm("fma.rn.f32x2 %0, %1, %2, %0;" : "+l"(d) : "l"(a), "l"(b));
}
__device__ __forceinline__ float2 u2f2(ull v) {
    float2 r; asm("mov.b64 {%0, %1}, %2;" : "=f"(r.x), "=f"(r.y) : "l"(v)); return r;
}

// ======================= 1) Farthest point sampling =======================
__global__ void fps_kernel(const float* __restrict__ xyz, float* __restrict__ out)
{
    extern __shared__ float sm[];
    float* xs = sm;
    float* ys = sm + NPTS;
    float* zs = sm + 2*NPTS;
    ull* wk = (ull*)(sm + 3*NPTS);
    int* farS = (int*)(wk + 16);

    const int b   = blockIdx.x;
    const int tid = threadIdx.x;
    const int lane = tid & 31, warp = tid >> 5;
    const float* X = xyz + (size_t)b * NPTS * 3;

    for (int i = tid; i < NPTS; i += 512) {
        xs[i] = X[i*3+0]; ys[i] = X[i*3+1]; zs[i] = X[i*3+2];
    }
    float dloc[8];
#pragma unroll
    for (int j = 0; j < 8; ++j) dloc[j] = 1e10f;
    __syncthreads();

    int far = 0;
    for (int it = 0; it < NP; ++it) {
        const float cx = xs[far], cy = ys[far], cz = zs[far];
        if (tid == 0) {
            const int o = (b*NP + it)*3;
            g_nxyz[o+0] = cx; g_nxyz[o+1] = cy; g_nxyz[o+2] = cz;
            out[o+0] = cx;    out[o+1] = cy;    out[o+2] = cz;
        }
        ull best = 0ull;
#pragma unroll
        for (int j = 0; j < 8; ++j) {
            const int p = tid + j*512;
            const float dx = xs[p]-cx, dy = ys[p]-cy, dz = zs[p]-cz;
            const float dd = dx*dx + dy*dy + dz*dz;
            const float nd = fminf(dloc[j], dd);
            dloc[j] = nd;
            const ull key = ((ull)__float_as_uint(nd) << 32) |
                            (ull)(0xFFFFFFFFu - (unsigned)p);
            best = (key > best) ? key : best;
        }
#pragma unroll
        for (int off = 16; off >= 1; off >>= 1) {
            ull o = __shfl_xor_sync(0xFFFFFFFFu, best, off);
            best = (o > best) ? o : best;
        }
        if (lane == 0) wk[warp] = best;
        __syncthreads();
        if (warp == 0) {
            ull v = (lane < 16) ? wk[lane] : 0ull;
#pragma unroll
            for (int off = 8; off >= 1; off >>= 1) {
                ull o = __shfl_xor_sync(0xFFFFFFFFu, v, off);
                v = (o > v) ? o : v;
            }
            if (lane == 0) farS[0] = (int)(0xFFFFFFFFu - (unsigned)v);
        }
        __syncthreads();
        far = farS[0];
    }
}

// ======================= 2) Ball query =======================
__global__ void qb_kernel(const float* __restrict__ xyz)
{
    const int w    = (blockIdx.x * blockDim.x + threadIdx.x) >> 5;
    const int lane = threadIdx.x & 31;
    const int b = w >> 10;
    const float* X = xyz + (size_t)b * NPTS * 3;
    const float cx = g_nxyz[w*3+0], cy = g_nxyz[w*3+1], cz = g_nxyz[w*3+2];
    int* g = g_gi + w*NS;

    int cnt = 0, first = -1;
    for (int r = 0; r < NPTS/32; ++r) {
        const int n = r*32 + lane;
        const float dx = X[n*3+0]-cx, dy = X[n*3+1]-cy, dz = X[n*3+2]-cz;
        const float d2 = dx*dx + dy*dy + dz*dz;
        const bool in = (d2 <= RAD2);
        const unsigned m = __ballot_sync(0xFFFFFFFFu, in);
        if (first < 0 && m) first = r*32 + __ffs(m) - 1;
        const int pos = cnt + __popc(m & ((1u << lane) - 1u));
        if (in && pos < NS) g[pos] = n;
        cnt += __popc(m);
        if (cnt >= NS) break;
    }
    for (int i = cnt + lane; i < NS; i += 32) g[i] = first;
}

// ======================= 3) F precompute: F = concat(xyz, pts) @ W0^T =======================
// 32768 rows x 64 out, K=67. f32x2 GEMM, transposed-X smem, duplicated weights.
__global__ __launch_bounds__(256) void fprep_kernel(const float* __restrict__ xyz,
                                                    const float* __restrict__ pts,
                                                    const float* __restrict__ W)
{
    extern __shared__ float smf[];
    float* XsT = smf;               // [67][130]
    float* WtD = smf + 67*130;      // [67][128]  duplicated pairs
    const int tid = threadIdx.x, blk = blockIdx.x;

    for (int i = tid; i < 67*64; i += 256) {
        const int n = i / 67, k = i - n*67;
        const float w = W[i];
        WtD[k*128 + 2*n] = w; WtD[k*128 + 2*n + 1] = w;
    }
    for (int i = tid; i < 128*67; i += 256) {
        const int lr = i / 67, c = i - lr*67;
        const int row = blk*128 + lr;
        const float v = (c < 3) ? xyz[row*3 + c] : pts[(size_t)row*64 + (c-3)];
        XsT[c*130 + lr] = v;
    }
    __syncthreads();

    const int tx = tid & 15, ty = tid >> 4;
    ull acc[4][4];
#pragma unroll
    for (int i = 0; i < 4; ++i)
#pragma unroll
        for (int j = 0; j < 4; ++j) acc[i][j] = 0ull;

#pragma unroll 4
    for (int k = 0; k < 67; ++k) {
        ull a[4], bv[4];
#pragma unroll
        for (int i2 = 0; i2 < 4; ++i2)
            a[i2] = *(const ull*)&XsT[k*130 + ty*8 + 2*i2];
#pragma unroll
        for (int j = 0; j < 4; ++j)
            bv[j] = *(const ull*)&WtD[k*128 + 2*(tx + 16*j)];
#pragma unroll
        for (int i2 = 0; i2 < 4; ++i2)
#pragma unroll
            for (int j = 0; j < 4; ++j) fma2(acc[i2][j], a[i2], bv[j]);
    }

    const int base = blk*128 + ty*8;
#pragma unroll
    for (int i2 = 0; i2 < 4; ++i2) {
        const int r0 = base + 2*i2;
#pragma unroll
        for (int j = 0; j < 4; ++j) {
            const float2 v = u2f2(acc[i2][j]);
            const int col = tx + 16*j;
            g_F[(size_t)r0*64 + col]     = v.x;
            g_F[(size_t)(r0+1)*64 + col] = v.y;
        }
    }
}

// ======================= 4) stats of layer0 (gathered F - C) =======================
__global__ __launch_bounds__(256) void stats0_kernel(const float* __restrict__ w0)
{
    __shared__ float sw[64*3];
    __shared__ float sd[4*64], sq_[4*64];
    const int tid = threadIdx.x, blk = blockIdx.x;
    for (int i = tid; i < 192; i += 256) sw[i] = w0[(i/3)*67 + (i%3)];
    __syncthreads();

    const int c = tid & 63, rg = tid >> 6;
    float s0 = 0.f, s1 = 0.f, q0 = 0.f, q1 = 0.f;
    int t = 0;
    for (int r = rg; r < 1024; r += 4, t ^= 1) {
        const int row = blk*1024 + r;
        const int b = row >> 15;
        const int qg = row >> 5;
        const int idx = g_gi[row];
        const float Cc = g_nxyz[qg*3+0]*sw[c*3+0]
                       + g_nxyz[qg*3+1]*sw[c*3+1]
                       + g_nxyz[qg*3+2]*sw[c*3+2];
        const float v = g_F[(((size_t)b<<12) + idx)*64 + c] - Cc;
        if (t) { s1 += v; q1 = fmaf(v, v, q1); }
        else   { s0 += v; q0 = fmaf(v, v, q0); }
    }
    sd[rg*64+c] = s0 + s1; sq_[rg*64+c] = q0 + q1;
    __syncthreads();
    if (tid < 64) {
        float s = sd[tid] + sd[64+tid] + sd[128+tid] + sd[192+tid];
        float q = sq_[tid] + sq_[64+tid] + sq_[128+tid] + sq_[192+tid];
        g_p0[blk*64 + tid] = make_float2(s, q);
    }
}

// ======================= finalize BN params (per-channel block) =======================
__global__ void finalize_kernel(int layer, int nblk,
                                const float* __restrict__ gam,
                                const float* __restrict__ bet)
{
    const float2* part = (layer == 0) ? g_p0 : ((layer == 1) ? g_p1 : g_p2);
    const int C = (layer == 2) ? 128 : 64;
    const int c = blockIdx.x;
    const int tid = threadIdx.x;
    __shared__ double sd[256], sq_[256];
    double s = 0.0, q = 0.0;
    for (int i = tid; i < nblk; i += 256) {
        const float2 v = part[i*C + c];
        s += (double)v.x; q += (double)v.y;
    }
    sd[tid] = s; sq_[tid] = q;
    __syncthreads();
    for (int off = 128; off; off >>= 1) {
        if (tid < off) { sd[tid] += sd[tid+off]; sq_[tid] += sq_[tid+off]; }
        __syncthreads();
    }
    if (tid == 0) {
        const double mu  = sd[0] / (double)MROWS;
        const double var = sq_[0] / (double)MROWS - mu*mu;
        const float rs = (float)rsqrt(var + 1e-5);
        const float sc = gam[c] * rs;
        if (layer == 0)      { g_sc0[c] = sc; g_sh0[c] = bet[c] - (float)mu*sc; }
        else if (layer == 1) { g_sc1[c] = sc; g_sh1[c] = bet[c] - (float)mu*sc; }
        else                 { g_sc2[c] = sc; g_sh2[c] = bet[c] - (float)mu*sc; }
    }
}

// ======================= 5) mm1: gather(F)-C -> bn0/relu -> @W1^T, + stats epilogue =======================
__global__ __launch_bounds__(256) void mm1_kernel(const float* __restrict__ w0,
                                                  const float* __restrict__ W)
{
    extern __shared__ float smf[];
    float* XsT = smf;               // [64][130]
    float* WtD = smf + 64*130;      // [64][128]
    float* ssum = WtD;              // alias after GEMM: [16][64]
    float* ssq  = WtD + 16*64;      // [16][64]
    __shared__ float sW0x[64*3];
    __shared__ float sCtr[4*3];
    __shared__ int   sIdx[128];

    const int tid = threadIdx.x, blk = blockIdx.x;

    for (int i = tid; i < 64*64; i += 256) {
        const int n = i >> 6, k = i & 63;
        const float w = W[i];
        WtD[k*128 + 2*n] = w; WtD[k*128 + 2*n + 1] = w;
    }
    if (tid < 192) sW0x[tid] = w0[(tid/3)*67 + (tid%3)];
    if (tid < 12)  sCtr[tid] = g_nxyz[(blk*4 + tid/3)*3 + (tid%3)];
    if (tid < 128) sIdx[tid] = g_gi[blk*128 + tid];
    __syncthreads();

    for (int i = tid; i < 128*64; i += 256) {
        const int c = i & 63, lr = i >> 6;
        const int row = blk*128 + lr;
        const int b = row >> 15;
        const int g = lr >> 5;
        const int idx = sIdx[lr];
        const float Cc = sCtr[g*3+0]*sW0x[c*3+0]
                       + sCtr[g*3+1]*sW0x[c*3+1]
                       + sCtr[g*3+2]*sW0x[c*3+2];
        float v = g_F[(((size_t)b<<12) + idx)*64 + c] - Cc;
        v = fmaxf(fmaf(v, g_sc0[c], g_sh0[c]), 0.f);
        XsT[c*130 + lr] = v;
    }
    __syncthreads();

    const int tx = tid & 15, ty = tid >> 4;
    ull acc[4][4];
#pragma unroll
    for (int i = 0; i < 4; ++i)
#pragma unroll
        for (int j = 0; j < 4; ++j) acc[i][j] = 0ull;

#pragma unroll 4
    for (int k = 0; k < 64; ++k) {
        ull a[4], bv[4];
#pragma unroll
        for (int i2 = 0; i2 < 4; ++i2)
            a[i2] = *(const ull*)&XsT[k*130 + ty*8 + 2*i2];
#pragma unroll
        for (int j = 0; j < 4; ++j)
            bv[j] = *(const ull*)&WtD[k*128 + 2*(tx + 16*j)];
#pragma unroll
        for (int i2 = 0; i2 < 4; ++i2)
#pragma unroll
            for (int j = 0; j < 4; ++j) fma2(acc[i2][j], a[i2], bv[j]);
    }

    // store Y1 + local stats (fixed order => deterministic)
    float ls[4], lq[4];
    const int base = blk*128 + ty*8;
#pragma unroll
    for (int j = 0; j < 4; ++j) {
        const int col = tx + 16*j;
        float s = 0.f, q = 0.f;
#pragma unroll
        for (int i2 = 0; i2 < 4; ++i2) {
            const float2 v = u2f2(acc[i2][j]);
            const int r0 = base + 2*i2;
            g_Y1[(size_t)r0*64 + col]     = v.x;
            g_Y1[(size_t)(r0+1)*64 + col] = v.y;
            s += v.x; s += v.y;
            q = fmaf(v.x, v.x, q); q = fmaf(v.y, v.y, q);
        }
        ls[j] = s; lq[j] = q;
    }
    __syncthreads();   // WtD no longer needed; safe to alias
#pragma unroll
    for (int j = 0; j < 4; ++j) {
        const int col = tx + 16*j;
        ssum[ty*64 + col] = ls[j];
        ssq [ty*64 + col] = lq[j];
    }
    __syncthreads();
    if (tid < 64) {
        float s = 0.f, q = 0.f;
#pragma unroll
        for (int t = 0; t < 16; ++t) { s += ssum[t*64 + tid]; q += ssq[t*64 + tid]; }
        g_p1[blk*64 + tid] = make_float2(s, q);
    }
}

// ======================= 6) mm2: bn1/relu(Y1) @ W2^T, + stats + in-block max-pool =======================
__global__ __launch_bounds__(256) void mm2_kernel(const float* __restrict__ W)
{
    extern __shared__ float smf[];
    float* XsT = smf;               // [64][130]
    float* WtD = smf + 64*130;      // [64][256]
    float* ssum = WtD;              // alias: [16][128]
    float* ssq  = WtD + 16*128;
    float* smax = WtD + 32*128;

    const int tid = threadIdx.x, blk = blockIdx.x;

    for (int i = tid; i < 128*64; i += 256) {
        const int n = i >> 6, k = i & 63;
        const float w = W[i];
        WtD[k*256 + 2*n] = w; WtD[k*256 + 2*n + 1] = w;
    }
    for (int i = tid; i < 128*64; i += 256) {
        const int c = i & 63, lr = i >> 6;
        const size_t row = (size_t)blk*128 + lr;
        float v = g_Y1[row*64 + c];
        v = fmaxf(fmaf(v, g_sc1[c], g_sh1[c]), 0.f);
        XsT[c*130 + lr] = v;
    }
    __syncthreads();

    const int tx = tid & 15, ty = tid >> 4;
    ull acc[4][8];
#pragma unroll
    for (int i = 0; i < 4; ++i)
#pragma unroll
        for (int j = 0; j < 8; ++j) acc[i][j] = 0ull;

#pragma unroll 2
    for (int k = 0; k < 64; ++k) {
        ull a[4], bv[8];
#pragma unroll
        for (int i2 = 0; i2 < 4; ++i2)
            a[i2] = *(const ull*)&XsT[k*130 + ty*8 + 2*i2];
#pragma unroll
        for (int j = 0; j < 8; ++j)
            bv[j] = *(const ull*)&WtD[k*256 + 2*(tx + 16*j)];
#pragma unroll
        for (int i2 = 0; i2 < 4; ++i2)
#pragma unroll
            for (int j = 0; j < 8; ++j) fma2(acc[i2][j], a[i2], bv[j]);
    }

    // local stats + max over this thread's 8 rows (all rows in one query group)
    float ls[8], lq[8], lm[8];
#pragma unroll
    for (int j = 0; j < 8; ++j) {
        float s = 0.f, q = 0.f, m = -3.4e38f;
#pragma unroll
        for (int i2 = 0; i2 < 4; ++i2) {
            const float2 v = u2f2(acc[i2][j]);
            s += v.x; s += v.y;
            q = fmaf(v.x, v.x, q); q = fmaf(v.y, v.y, q);
            m = fmaxf(m, fmaxf(v.x, v.y));
        }
        ls[j] = s; lq[j] = q; lm[j] = m;
    }
    __syncthreads();
#pragma unroll
    for (int j = 0; j < 8; ++j) {
        const int col = tx + 16*j;
        ssum[ty*128 + col] = ls[j];
        ssq [ty*128 + col] = lq[j];
        smax[ty*128 + col] = lm[j];
    }
    __syncthreads();
    if (tid < 128) {
        float s = 0.f, q = 0.f;
#pragma unroll
        for (int t = 0; t < 16; ++t) { s += ssum[t*128 + tid]; q += ssq[t*128 + tid]; }
        g_p2[blk*128 + tid] = make_float2(s, q);
    }
    for (int w = tid; w < 512; w += 256) {
        const int g = w >> 7, col = w & 127;
        float m = smax[(4*g+0)*128 + col];
        m = fmaxf(m, smax[(4*g+1)*128 + col]);
        m = fmaxf(m, smax[(4*g+2)*128 + col]);
        m = fmaxf(m, smax[(4*g+3)*128 + col]);
        g_max[(blk*4 + g)*128 + col] = m;
    }
}

// ======================= 7) final pool: bn2+relu on per-query max =======================
__global__ void pool_kernel(float* __restrict__ out)
{
    const int i = blockIdx.x * 1024 + threadIdx.x;   // < 8192*128
    const int c = i & 127;
    const float v = fmaxf(fmaf(g_max[i], g_sc2[c], g_sh2[c]), 0.f);
    out[NQ*3 + i] = v;
}

// ======================= launch =======================
extern "C" void kernel_launch(void* const* d_in, const int* in_sizes, int n_in,
                              void* d_out, int out_size)
{
    const float* xyz = (const float*)d_in[0];
    const float* pts = (const float*)d_in[1];
    const float* w0  = (const float*)d_in[2];
    const float* gm0 = (const float*)d_in[4];
    const float* bt0 = (const float*)d_in[5];
    const float* w1  = (const float*)d_in[6];
    const float* gm1 = (const float*)d_in[8];
    const float* bt1 = (const float*)d_in[9];
    const float* w2  = (const float*)d_in[10];
    const float* gm2 = (const float*)d_in[12];
    const float* bt2 = (const float*)d_in[13];
    float* out = (float*)d_out;

    const int smF  = 67*130*4 + 67*128*4;   // 69144
    const int smM1 = 64*130*4 + 64*128*4;   // 66048
    const int smM2 = 64*130*4 + 64*256*4;   // 98816

    cudaFuncSetAttribute(fps_kernel,  cudaFuncAttributeMaxDynamicSharedMemorySize, 49536);
    cudaFuncSetAttribute(fprep_kernel, cudaFuncAttributeMaxDynamicSharedMemorySize, smF);
    cudaFuncSetAttribute(mm1_kernel,  cudaFuncAttributeMaxDynamicSharedMemorySize, smM1);
    cudaFuncSetAttribute(mm2_kernel,  cudaFuncAttributeMaxDynamicSharedMemorySize, smM2);

    fprep_kernel<<<NSRC/128, 256, smF>>>(xyz, pts, w0);
    fps_kernel<<<BATCH, 512, 49536>>>(xyz, out);
    qb_kernel<<<(NQ*32)/256, 256>>>(xyz);

    stats0_kernel<<<256, 256>>>(w0);
    finalize_kernel<<<64, 256>>>(0, 256, gm0, bt0);

    mm1_kernel<<<MROWS/128, 256, smM1>>>(w0, w1);
    finalize_kernel<<<64, 256>>>(1, 2048, gm1, bt1);

    mm2_kernel<<<MROWS/128, 256, smM2>>>(w2);
    finalize_kernel<<<128, 256>>>(2, 2048, gm2, bt2);

    pool_kernel<<<(NQ*128)/1024, 1024>>>(out);
}

// round 5
// speedup vs baseline: 1.9243x; 1.2456x over previous
#include <cuda_runtime.h>

#define BATCH   8
#define NPTS    4096
#define NP      1024
#define NS      32
#define MROWS   262144
#define NQ      8192
#define NSRC    32768
#define RAD2    0.04f

typedef unsigned long long ull;
typedef unsigned int uint;

// ---------------- device scratch ----------------
__device__ float  g_F[NSRC*64];
__device__ float  g_Y1[(size_t)MROWS*64];
__device__ float  g_max[NQ*128];
__device__ float  g_nxyz[NQ*3];
__device__ int    g_gi[MROWS];
__device__ float2 g_p0[2048*64];
__device__ float2 g_p1[1024*64];
__device__ float2 g_p2[2048*128];
__device__ float  g_sc0[64], g_sh0[64];
__device__ float  g_sc1[64], g_sh1[64];
__device__ float  g_sc2[128], g_sh2[128];

// ---------------- helpers ----------------
__device__ __forceinline__ void fma2(ull& d, ull a, ull b) {
    asm("fma.rn.f32x2 %0, %1, %2, %0;" : "+l"(d) : "l"(a), "l"(b));
}
__device__ __forceinline__ float2 u2f2(ull v) {
    float2 r; asm("mov.b64 {%0, %1}, %2;" : "=f"(r.x), "=f"(r.y) : "l"(v)); return r;
}
__device__ __forceinline__ uint rmax(uint v) {
    uint r; asm("redux.sync.max.u32 %0, %1, 0xffffffff;" : "=r"(r) : "r"(v)); return r;
}
__device__ __forceinline__ uint rmin(uint v) {
    uint r; asm("redux.sync.min.u32 %0, %1, 0xffffffff;" : "=r"(r) : "r"(v)); return r;
}

// ======================= 1a) FPS (register-resident) =======================
__device__ void fps_block(const float* __restrict__ xyz, float* __restrict__ out,
                          float* sm, int b)
{
    float* xs = sm;
    float* ys = sm + NPTS;
    float* zs = sm + 2*NPTS;
    uint* wkd = (uint*)(sm + 3*NPTS);   // [2][16]
    uint* wki = wkd + 32;               // [2][16]

    const int tid  = threadIdx.x;       // 512
    const int lane = tid & 31;
    const int warp = tid >> 5;          // 16
    const float* X = xyz + (size_t)b * NPTS * 3;

    for (int i = tid; i < NPTS; i += 512) {
        xs[i] = X[i*3+0]; ys[i] = X[i*3+1]; zs[i] = X[i*3+2];
    }
    __syncthreads();

    float rx[8], ry[8], rz[8], dl[8];
#pragma unroll
    for (int j = 0; j < 8; ++j) {
        const int p = tid + j*512;
        rx[j] = xs[p]; ry[j] = ys[p]; rz[j] = zs[p];
        dl[j] = 1e10f;
    }

    int far = 0, buf = 0;
    for (int it = 0; it < NP; ++it) {
        const float cx = xs[far], cy = ys[far], cz = zs[far];
        if (tid == 0) {
            const int o = (b*NP + it)*3;
            g_nxyz[o+0] = cx; g_nxyz[o+1] = cy; g_nxyz[o+2] = cz;
            out[o+0] = cx;    out[o+1] = cy;    out[o+2] = cz;
        }
#pragma unroll
        for (int j = 0; j < 8; ++j) {
            const float dx = rx[j]-cx, dy = ry[j]-cy, dz = rz[j]-cz;
            const float dd = dx*dx + dy*dy + dz*dz;   // identical expr to passing kernel
            dl[j] = fminf(dl[j], dd);
        }
        const float t01 = fmaxf(dl[0], dl[1]), t23 = fmaxf(dl[2], dl[3]);
        const float t45 = fmaxf(dl[4], dl[5]), t67 = fmaxf(dl[6], dl[7]);
        const float tmax = fmaxf(fmaxf(t01, t23), fmaxf(t45, t67));
        int idx = tid + 7*512;
#pragma unroll
        for (int j = 6; j >= 0; --j) idx = (dl[j] == tmax) ? (tid + j*512) : idx;

        const uint tb   = __float_as_uint(tmax);        // dists >= 0 -> bits monotone
        const uint wmax = rmax(tb);
        const uint wi   = rmin((tb == wmax) ? (uint)idx : 0x7fffffffu);
        if (lane == 0) { wkd[buf*16 + warp] = wmax; wki[buf*16 + warp] = wi; }
        __syncthreads();
        const uint dd2 = (lane < 16) ? wkd[buf*16 + lane] : 0u;
        const uint ii2 = (lane < 16) ? wki[buf*16 + lane] : 0x7fffffffu;
        const uint bmax = rmax(dd2);
        far = (int)rmin((dd2 == bmax) ? ii2 : 0x7fffffffu);
        buf ^= 1;
    }
}

// ======================= 1b) fprep: F = concat(xyz, pts) @ W0^T =======================
__device__ void fprep_block(const float* __restrict__ xyz, const float* __restrict__ pts,
                            const float* __restrict__ W, float* smf, int blk)
{
    float* XsT = smf;               // [67][130]
    float* WtD = smf + 67*130;      // [67][128] permuted dup pairs
    const int tid = threadIdx.x;    // 512

    // col n stored at word 2*((n&3)*16 + (n>>2)) -> thread cols contiguous 4tx..4tx+3
    for (int i = tid; i < 67*64; i += 512) {
        const int n = i / 67, k = i - n*67;
        const float w = W[i];
        const int p = 2*((n & 3)*16 + (n >> 2));
        WtD[k*128 + p] = w; WtD[k*128 + p + 1] = w;
    }
    for (int i = tid; i < 128*67; i += 512) {
        const int lr = i / 67, c = i - lr*67;
        const int row = blk*128 + lr;
        const float v = (c < 3) ? xyz[row*3 + c] : pts[(size_t)row*64 + (c-3)];
        XsT[c*130 + lr] = v;
    }
    __syncthreads();

    const int tx = tid & 15;   // 16 colgroups x 4
    const int ty = tid >> 4;   // 32 rowgroups x 4
    ull acc[2][4] = {};
#pragma unroll 4
    for (int k = 0; k < 67; ++k) {
        ull a[2], bv[4];
#pragma unroll
        for (int i2 = 0; i2 < 2; ++i2) a[i2] = *(const ull*)&XsT[k*130 + ty*4 + 2*i2];
#pragma unroll
        for (int j = 0; j < 4; ++j)    bv[j] = *(const ull*)&WtD[k*128 + 2*(j*16 + tx)];
#pragma unroll
        for (int i2 = 0; i2 < 2; ++i2)
#pragma unroll
            for (int j = 0; j < 4; ++j) fma2(acc[i2][j], a[i2], bv[j]);
    }
    const int rbase = blk*128 + ty*4;
#pragma unroll
    for (int i2 = 0; i2 < 2; ++i2) {
        float2 t[4];
#pragma unroll
        for (int j = 0; j < 4; ++j) t[j] = u2f2(acc[i2][j]);   // col = 4*tx + j
        const int r = rbase + 2*i2;
        *(float4*)&g_F[(size_t)r*64 + tx*4]     = make_float4(t[0].x, t[1].x, t[2].x, t[3].x);
        *(float4*)&g_F[(size_t)(r+1)*64 + tx*4] = make_float4(t[0].y, t[1].y, t[2].y, t[3].y);
    }
}

__global__ __launch_bounds__(512) void fused_fps_fprep(const float* __restrict__ xyz,
                                                       const float* __restrict__ pts,
                                                       const float* __restrict__ w0,
                                                       float* __restrict__ out)
{
    extern __shared__ float sm[];
    if (blockIdx.x < 8) fps_block(xyz, out, sm, blockIdx.x);
    else                fprep_block(xyz, pts, w0, sm, blockIdx.x - 8);
}

// ======================= 2) Ball query =======================
__global__ void qb_kernel(const float* __restrict__ xyz)
{
    const int w    = (blockIdx.x * blockDim.x + threadIdx.x) >> 5;
    const int lane = threadIdx.x & 31;
    const int b = w >> 10;
    const float* X = xyz + (size_t)b * NPTS * 3;
    const float cx = g_nxyz[w*3+0], cy = g_nxyz[w*3+1], cz = g_nxyz[w*3+2];
    int* g = g_gi + w*NS;

    int cnt = 0, first = -1;
    for (int r = 0; r < NPTS/32; ++r) {
        const int n = r*32 + lane;
        const float dx = X[n*3+0]-cx, dy = X[n*3+1]-cy, dz = X[n*3+2]-cz;
        const float d2 = dx*dx + dy*dy + dz*dz;
        const bool in = (d2 <= RAD2);
        const unsigned m = __ballot_sync(0xFFFFFFFFu, in);
        if (first < 0 && m) first = r*32 + __ffs(m) - 1;
        const int pos = cnt + __popc(m & ((1u << lane) - 1u));
        if (in && pos < NS) g[pos] = n;
        cnt += __popc(m);
        if (cnt >= NS) break;
    }
    for (int i = cnt + lane; i < NS; i += 32) g[i] = first;
}

// ======================= 3) layer-0 stats =======================
__global__ __launch_bounds__(256) void stats0_kernel(const float* __restrict__ w0)
{
    __shared__ float sw[192];
    __shared__ float sd[256], sq[256];
    const int tid = threadIdx.x, blk = blockIdx.x;
    for (int i = tid; i < 192; i += 256) sw[i] = w0[(i/3)*67 + (i%3)];
    __syncthreads();

    const int c = tid & 63, rg = tid >> 6;
    float s = 0.f, q = 0.f;
#pragma unroll 4
    for (int r = rg; r < 128; r += 4) {
        const int row = blk*128 + r;
        const int b = row >> 15;
        const int qg = row >> 5;
        const int idx = g_gi[row];
        const float Cc = g_nxyz[qg*3+0]*sw[c*3+0]
                       + g_nxyz[qg*3+1]*sw[c*3+1]
                       + g_nxyz[qg*3+2]*sw[c*3+2];
        const float v = g_F[(((size_t)b << 12) + idx)*64 + c] - Cc;
        s += v; q = fmaf(v, v, q);
    }
    sd[tid] = s; sq[tid] = q;
    __syncthreads();
    if (tid < 64) {
        g_p0[blk*64 + tid] = make_float2(sd[tid] + sd[64+tid] + sd[128+tid] + sd[192+tid],
                                         sq[tid] + sq[64+tid] + sq[128+tid] + sq[192+tid]);
    }
}

// ======================= finalize BN =======================
__global__ void finalize_kernel(int layer, int nblk,
                                const float* __restrict__ gam,
                                const float* __restrict__ bet)
{
    const float2* part = (layer == 0) ? g_p0 : ((layer == 1) ? g_p1 : g_p2);
    const int C = (layer == 2) ? 128 : 64;
    const int c = blockIdx.x;
    const int tid = threadIdx.x;
    __shared__ double sd[256], sq[256];
    double s = 0.0, q = 0.0;
    for (int i = tid; i < nblk; i += 256) {
        const float2 v = part[i*C + c];
        s += (double)v.x; q += (double)v.y;
    }
    sd[tid] = s; sq[tid] = q;
    __syncthreads();
    for (int off = 128; off; off >>= 1) {
        if (tid < off) { sd[tid] += sd[tid+off]; sq[tid] += sq[tid+off]; }
        __syncthreads();
    }
    if (tid == 0) {
        const double mu  = sd[0] / (double)MROWS;
        const double var = sq[0] / (double)MROWS - mu*mu;
        const float rs = (float)rsqrt(var + 1e-5);
        const float sc = gam[c] * rs;
        if (layer == 0)      { g_sc0[c] = sc; g_sh0[c] = bet[c] - (float)mu*sc; }
        else if (layer == 1) { g_sc1[c] = sc; g_sh1[c] = bet[c] - (float)mu*sc; }
        else                 { g_sc2[c] = sc; g_sh2[c] = bet[c] - (float)mu*sc; }
    }
}

// ======================= 4) mm1 =======================
// 256 rows x 64 cols, 128 threads, tile 16x8, 2 blocks/SM.
__global__ __launch_bounds__(128, 2) void mm1_kernel(const float* __restrict__ w0,
                                                     const float* __restrict__ W)
{
    extern __shared__ float smf[];
    float* XsT  = smf;              // [64][258]
    float* WtD  = smf + 64*258;     // [64][128]
    float* ssum = WtD;              // alias post-GEMM [16][64]
    float* ssq  = WtD + 16*64;
    __shared__ float sW0x[192];
    __shared__ float sCtr[24];
    __shared__ int   sIdx[256];

    const int tid = threadIdx.x, blk = blockIdx.x;

    // col n at word 2*((n&7)*8 + (n>>3)) -> thread cols contiguous 8tx..8tx+7
    for (int i = tid; i < 64*64; i += 128) {
        const int n = i >> 6, k = i & 63;
        const float w = W[i];
        const int p = 2*((n & 7)*8 + (n >> 3));
        WtD[k*128 + p] = w; WtD[k*128 + p + 1] = w;
    }
    for (int i = tid; i < 192; i += 128) sW0x[i] = w0[(i/3)*67 + (i%3)];
    if (tid < 24) sCtr[tid] = g_nxyz[(blk*8 + tid/3)*3 + (tid%3)];
    for (int i = tid; i < 256; i += 128) sIdx[i] = g_gi[blk*256 + i];
    __syncthreads();

    const int bb = blk >> 7;   // batch (128 blocks per batch)
    for (int i = tid; i < 256*64; i += 128) {
        const int lr = i >> 6, c = i & 63;
        const int g = lr >> 5;
        const int idx = sIdx[lr];
        const float Cc = sCtr[g*3+0]*sW0x[c*3+0]
                       + sCtr[g*3+1]*sW0x[c*3+1]
                       + sCtr[g*3+2]*sW0x[c*3+2];
        float v = g_F[(((size_t)bb << 12) + idx)*64 + c] - Cc;
        v = fmaxf(fmaf(v, g_sc0[c], g_sh0[c]), 0.f);
        XsT[c*258 + lr] = v;
    }
    __syncthreads();

    const int tx = tid & 7, ty = tid >> 3;   // 8 colgroups, 16 rowgroups
    ull acc[8][8] = {};
#pragma unroll 1
    for (int k = 0; k < 64; ++k) {
        ull a[8], bv[8];
#pragma unroll
        for (int i2 = 0; i2 < 8; ++i2) a[i2] = *(const ull*)&XsT[k*258 + ty*16 + 2*i2];
#pragma unroll
        for (int j = 0; j < 8; ++j)    bv[j] = *(const ull*)&WtD[k*128 + 2*(j*8 + tx)];
#pragma unroll
        for (int i2 = 0; i2 < 8; ++i2)
#pragma unroll
            for (int j = 0; j < 8; ++j) fma2(acc[i2][j], a[i2], bv[j]);
    }

    float ls[8], lq[8];
#pragma unroll
    for (int j = 0; j < 8; ++j) {
        float s = 0.f, q = 0.f;
#pragma unroll
        for (int i2 = 0; i2 < 8; ++i2) {
            const float2 v = u2f2(acc[i2][j]);
            s += v.x; s += v.y;
            q = fmaf(v.x, v.x, q); q = fmaf(v.y, v.y, q);
        }
        ls[j] = s; lq[j] = q;
    }
    const int rbase = blk*256 + ty*16;
#pragma unroll
    for (int i2 = 0; i2 < 8; ++i2) {
        float2 t[8];
#pragma unroll
        for (int j = 0; j < 8; ++j) t[j] = u2f2(acc[i2][j]);   // col = 8*tx + j
        const int r = rbase + 2*i2;
        float* y0 = &g_Y1[(size_t)r*64 + tx*8];
        ((float4*)y0)[0] = make_float4(t[0].x, t[1].x, t[2].x, t[3].x);
        ((float4*)y0)[1] = make_float4(t[4].x, t[5].x, t[6].x, t[7].x);
        float* y1 = &g_Y1[(size_t)(r+1)*64 + tx*8];
        ((float4*)y1)[0] = make_float4(t[0].y, t[1].y, t[2].y, t[3].y);
        ((float4*)y1)[1] = make_float4(t[4].y, t[5].y, t[6].y, t[7].y);
    }
    __syncthreads();   // WtD done -> alias
#pragma unroll
    for (int j = 0; j < 8; ++j) {
        ssum[ty*64 + tx*8 + j] = ls[j];
        ssq [ty*64 + tx*8 + j] = lq[j];
    }
    __syncthreads();
    if (tid < 64) {
        float s = 0.f, q = 0.f;
#pragma unroll
        for (int t = 0; t < 16; ++t) { s += ssum[t*64 + tid]; q += ssq[t*64 + tid]; }
        g_p1[blk*64 + tid] = make_float2(s, q);
    }
}

// ======================= 5) mm2 (+stats +max-pool) =======================
// 128 rows x 128 cols, 128 threads, tile 16x8.
__global__ __launch_bounds__(128, 2) void mm2_kernel(const float* __restrict__ W)
{
    extern __shared__ float smf[];
    float* XsT  = smf;              // [64][130]
    float* WtD  = smf + 64*130;     // [64][256]
    float* ssum = WtD;              // alias [8][128]
    float* ssq  = WtD + 8*128;
    float* smax = WtD + 16*128;

    const int tid = threadIdx.x, blk = blockIdx.x;

    // col n at word 2*((n&7)*16 + (n>>3)) -> thread cols contiguous 8tx..8tx+7
    for (int i = tid; i < 128*64; i += 128) {
        const int n = i >> 6, k = i & 63;
        const float w = W[i];
        const int p = 2*((n & 7)*16 + (n >> 3));
        WtD[k*256 + p] = w; WtD[k*256 + p + 1] = w;
    }
    for (int i = tid; i < 128*64; i += 128) {
        const int lr = i >> 6, c = i & 63;
        float v = g_Y1[((size_t)blk*128 + lr)*64 + c];
        v = fmaxf(fmaf(v, g_sc1[c], g_sh1[c]), 0.f);
        XsT[c*130 + lr] = v;
    }
    __syncthreads();

    const int tx = tid & 15, ty = tid >> 4;   // 16 colgroups, 8 rowgroups
    ull acc[8][8] = {};
#pragma unroll 1
    for (int k = 0; k < 64; ++k) {
        ull a[8], bv[8];
#pragma unroll
        for (int i2 = 0; i2 < 8; ++i2) a[i2] = *(const ull*)&XsT[k*130 + ty*16 + 2*i2];
#pragma unroll
        for (int j = 0; j < 8; ++j)    bv[j] = *(const ull*)&WtD[k*256 + 2*(j*16 + tx)];
#pragma unroll
        for (int i2 = 0; i2 < 8; ++i2)
#pragma unroll
            for (int j = 0; j < 8; ++j) fma2(acc[i2][j], a[i2], bv[j]);
    }

    // cols = 8*tx + j; rows ty*16..ty*16+15 (half a query group)
    float ls[8], lq[8], lm[8];
#pragma unroll
    for (int j = 0; j < 8; ++j) {
        float s = 0.f, q = 0.f, m = -3.4e38f;
#pragma unroll
        for (int i2 = 0; i2 < 8; ++i2) {
            const float2 v = u2f2(acc[i2][j]);
            s += v.x; s += v.y;
            q = fmaf(v.x, v.x, q); q = fmaf(v.y, v.y, q);
            m = fmaxf(m, fmaxf(v.x, v.y));
        }
        ls[j] = s; lq[j] = q; lm[j] = m;
    }
    __syncthreads();   // WtD done -> alias
#pragma unroll
    for (int j = 0; j < 8; ++j) {
        const int c = tx*8 + j;
        ssum[ty*128 + c] = ls[j];
        ssq [ty*128 + c] = lq[j];
        smax[ty*128 + c] = lm[j];
    }
    __syncthreads();
    if (tid < 128) {
        float s = 0.f, q = 0.f;
#pragma unroll
        for (int t = 0; t < 8; ++t) { s += ssum[t*128 + tid]; q += ssq[t*128 + tid]; }
        g_p2[blk*128 + tid] = make_float2(s, q);
    }
    for (int w = tid; w < 512; w += 128) {
        const int g = w >> 7, c = w & 127;
        const float m = fmaxf(smax[(2*g)*128 + c], smax[(2*g+1)*128 + c]);
        g_max[(blk*4 + g)*128 + c] = m;
    }
}

// ======================= 6) final pool =======================
__global__ void pool_kernel(float* __restrict__ out)
{
    const int i = blockIdx.x * 1024 + threadIdx.x;
    const int c = i & 127;
    out[NQ*3 + i] = fmaxf(fmaf(g_max[i], g_sc2[c], g_sh2[c]), 0.f);
}

// ======================= launch =======================
extern "C" void kernel_launch(void* const* d_in, const int* in_sizes, int n_in,
                              void* d_out, int out_size)
{
    const float* xyz = (const float*)d_in[0];
    const float* pts = (const float*)d_in[1];
    const float* w0  = (const float*)d_in[2];
    const float* gm0 = (const float*)d_in[4];
    const float* bt0 = (const float*)d_in[5];
    const float* w1  = (const float*)d_in[6];
    const float* gm1 = (const float*)d_in[8];
    const float* bt1 = (const float*)d_in[9];
    const float* w2  = (const float*)d_in[10];
    const float* gm2 = (const float*)d_in[12];
    const float* bt2 = (const float*)d_in[13];
    float* out = (float*)d_out;

    const int smFU = 67*130*4 + 67*128*4;   // 69144 (>= fps's 49408)
    const int smM1 = 64*258*4 + 64*128*4;   // 98816
    const int smM2 = 64*130*4 + 64*256*4;   // 98816

    cudaFuncSetAttribute(fused_fps_fprep, cudaFuncAttributeMaxDynamicSharedMemorySize, smFU);
    cudaFuncSetAttribute(mm1_kernel, cudaFuncAttributeMaxDynamicSharedMemorySize, smM1);
    cudaFuncSetAttribute(mm2_kernel, cudaFuncAttributeMaxDynamicSharedMemorySize, smM2);

    fused_fps_fprep<<<8 + NSRC/128, 512, smFU>>>(xyz, pts, w0, out);
    qb_kernel<<<(NQ*32)/256, 256>>>(xyz);

    stats0_kernel<<<2048, 256>>>(w0);
    finalize_kernel<<<64, 256>>>(0, 2048, gm0, bt0);

    mm1_kernel<<<MROWS/256, 128, smM1>>>(w0, w1);
    finalize_kernel<<<64, 256>>>(1, 1024, gm1, bt1);

    mm2_kernel<<<MROWS/128, 128, smM2>>>(w2);
    finalize_kernel<<<128, 256>>>(2, 2048, gm2, bt2);

    pool_kernel<<<(NQ*128)/1024, 1024>>>(out);
}